// round 8
// baseline (speedup 1.0000x reference)
#include <cuda_runtime.h>
#include <cuda_fp16.h>
#include <math.h>
#include <stdint.h>

// ---------------- problem constants ----------------
#define BATCH 4
#define SEQ   2048
#define DIM   1024
#define NH    8
#define HD    128
#define WIN   16
#define EPSV  1e-6f
#define MR    (BATCH*SEQ)   // 8192
#define NQKV  3072
#define NW    4096          // transposed weight rows: 3072 qkv + 1024 wo

// ---------------- device scratch ----------------
__device__ __align__(16) __half g_wT[NW*DIM];     // fp16 transposed weights [n][k]
__device__ __align__(16) __half g_xh[MR*DIM];
__device__ __align__(16) float  g_qkv[MR*NQKV];
__device__ __align__(16) __half g_yh[MR*DIM];

// ---------------- PTX helpers ----------------
__device__ __forceinline__ uint32_t smem_u32(const void* p) {
    uint32_t a;
    asm("{ .reg .u64 t; cvta.to.shared.u64 t, %1; cvt.u32.u64 %0, t; }" : "=r"(a) : "l"(p));
    return a;
}
__device__ __forceinline__ void cp16(uint32_t d, const void* s) {
    asm volatile("cp.async.cg.shared.global [%0], [%1], 16;" :: "r"(d), "l"(s));
}
__device__ __forceinline__ void cp_commit() { asm volatile("cp.async.commit_group;" ::: "memory"); }
__device__ __forceinline__ void cp_wait2()  { asm volatile("cp.async.wait_group 2;" ::: "memory"); }
__device__ __forceinline__ void cp_wait1()  { asm volatile("cp.async.wait_group 1;" ::: "memory"); }
__device__ __forceinline__ void cp_wait0()  { asm volatile("cp.async.wait_group 0;" ::: "memory"); }

__device__ __forceinline__ void ldm_x4(uint32_t* r, uint32_t addr) {
    asm volatile("ldmatrix.sync.aligned.m8n8.x4.shared.b16 {%0,%1,%2,%3}, [%4];"
                 : "=r"(r[0]), "=r"(r[1]), "=r"(r[2]), "=r"(r[3]) : "r"(addr));
}
__device__ __forceinline__ void mma_f16(float* c, const uint32_t* a, const uint32_t* b) {
    asm volatile(
        "mma.sync.aligned.m16n8k16.row.col.f32.f16.f16.f32 "
        "{%0,%1,%2,%3}, {%4,%5,%6,%7}, {%8,%9}, {%0,%1,%2,%3};"
        : "+f"(c[0]), "+f"(c[1]), "+f"(c[2]), "+f"(c[3])
        : "r"(a[0]), "r"(a[1]), "r"(a[2]), "r"(a[3]), "r"(b[0]), "r"(b[1]));
}

// ---------------- transpose all 4 weights -> g_wT fp16 [n][k] ----------------
__global__ __launch_bounds__(256)
void transpose_all(const float* __restrict__ wq, const float* __restrict__ wk,
                   const float* __restrict__ wv, const float* __restrict__ wo,
                   __half* __restrict__ wT)
{
    __shared__ float t[32][33];
    const float* W = (blockIdx.z == 0) ? wq : (blockIdx.z == 1) ? wk
                    : (blockIdx.z == 2) ? wv : wo;
    __half* out = wT + (size_t)blockIdx.z * DIM * DIM;
    const int c0 = blockIdx.x * 32, r0 = blockIdx.y * 32;
    const int tx = threadIdx.x, ty = threadIdx.y;
#pragma unroll
    for (int j = 0; j < 4; j++)
        t[ty + 8*j][tx] = W[(size_t)(r0 + ty + 8*j) * DIM + c0 + tx];
    __syncthreads();
#pragma unroll
    for (int j = 0; j < 4; j++)
        out[(size_t)(c0 + ty + 8*j) * DIM + (r0 + tx)] = __float2half_rn(t[tx][ty + 8*j]);
}

// ---------------- fp32 -> fp16 convert ----------------
__global__ __launch_bounds__(256)
void cvt16(const float* __restrict__ x, __half* __restrict__ hi, int n4)
{
    int i = blockIdx.x * 256 + threadIdx.x;
    if (i >= n4) return;
    float4 v = ((const float4*)x)[i];
    __half2 H0; H0.x = __float2half_rn(v.x); H0.y = __float2half_rn(v.y);
    __half2 H1; H1.x = __float2half_rn(v.z); H1.y = __float2half_rn(v.w);
    ((__half2*)hi)[2*i]   = H0;
    ((__half2*)hi)[2*i+1] = H1;
}

// ---------------- fp16 warp-MMA GEMM: C = A @ B^T ----------------
// CTA 128x128, BK=32 fp16, 4-stage cp.async, 4 warps of 64x64, 2 CTAs/SM.
#define TILEB  8192              // 128 rows x 64 bytes
#define STAGEB (2*TILEB)         // A, B
#define GSMEM  (4*STAGEB)        // 65536

__device__ __forceinline__ uint32_t swz_addr(uint32_t tile, int row, int chunk) {
    return tile + row * 64 + (((uint32_t)(chunk ^ ((row >> 1) & 3))) << 4);
}

__global__ __launch_bounds__(128, 2)
void gemm_f16(const __half* __restrict__ a, const __half* __restrict__ b,
              float* __restrict__ C, int ldc)
{
    extern __shared__ char smem[];
    const uint32_t sbase = smem_u32(smem);
    const int tid  = threadIdx.x;
    const int lane = tid & 31;
    const int wid  = tid >> 5;
    const int wm   = wid >> 1;          // 0..1 -> 64-row strip
    const int wn   = wid & 1;           // 0..1 -> 64-col strip
    const int m0 = blockIdx.y * 128;
    const int n0 = blockIdx.x * 128;

    // loader: thread t owns row t of both tiles, 4 chunks each
    const int lrow = tid;               // 0..127
    const __half* asrc = a + (size_t)(m0 + lrow) * DIM;
    const __half* bsrc = b + (size_t)(n0 + lrow) * DIM;

    // fragment addressing
    int arow[4], browx[4];
#pragma unroll
    for (int mt = 0; mt < 4; mt++) arow[mt] = wm * 64 + mt * 16 + (lane & 15);
#pragma unroll
    for (int p = 0; p < 4; p++)
        browx[p] = wn * 64 + p * 16 + ((lane >> 4) << 3) + (lane & 7);
    const int ac = lane >> 4;           // A chunk selector
    const int bc = (lane >> 3) & 1;     // B chunk selector

    float acc[4][8][4];
#pragma unroll
    for (int mt = 0; mt < 4; mt++)
#pragma unroll
        for (int nt = 0; nt < 8; nt++)
#pragma unroll
            for (int q = 0; q < 4; q++) acc[mt][nt][q] = 0.0f;

#pragma unroll
    for (int s = 0; s < 3; s++) {
        const uint32_t st = sbase + s * STAGEB;
        const int k0 = s * 32;
#pragma unroll
        for (int c = 0; c < 4; c++) {
            cp16(swz_addr(st,         lrow, c), asrc + k0 + c * 8);
            cp16(swz_addr(st + TILEB, lrow, c), bsrc + k0 + c * 8);
        }
        cp_commit();
    }

    const int NIT = DIM / 32;           // 32
    for (int i = 0; i < NIT; i++) {
        if (i < NIT - 2)      cp_wait2();
        else if (i == NIT-2)  cp_wait1();
        else                  cp_wait0();
        __syncthreads();

        if (i + 3 < NIT) {
            const uint32_t st = sbase + ((i + 3) & 3) * STAGEB;
            const int k0 = (i + 3) * 32;
#pragma unroll
            for (int c = 0; c < 4; c++) {
                cp16(swz_addr(st,         lrow, c), asrc + k0 + c * 8);
                cp16(swz_addr(st + TILEB, lrow, c), bsrc + k0 + c * 8);
            }
            cp_commit();
        }

        const uint32_t st = sbase + (i & 3) * STAGEB;
        const uint32_t sA = st;
        const uint32_t sB = st + TILEB;

#pragma unroll
        for (int kh = 0; kh < 2; kh++) {
            // B: 4 x ldm_x4, each covering two n-tiles (16 cols x k16)
            uint32_t fB[4][4], fA[4][4];
#pragma unroll
            for (int p = 0; p < 4; p++)
                ldm_x4(fB[p], swz_addr(sB, browx[p], kh * 2 + bc));
#pragma unroll
            for (int mt = 0; mt < 4; mt++)
                ldm_x4(fA[mt], swz_addr(sA, arow[mt], kh * 2 + ac));
#pragma unroll
            for (int mt = 0; mt < 4; mt++)
#pragma unroll
                for (int p = 0; p < 4; p++) {
                    mma_f16(acc[mt][p*2],     fA[mt], &fB[p][0]);
                    mma_f16(acc[mt][p*2 + 1], fA[mt], &fB[p][2]);
                }
        }
    }

    const int erow = lane >> 2;
    const int ecol = (lane & 3) * 2;
#pragma unroll
    for (int mt = 0; mt < 4; mt++) {
#pragma unroll
        for (int nt = 0; nt < 8; nt++) {
            const int r0 = m0 + wm * 64 + mt * 16 + erow;
            const int c0 = n0 + wn * 64 + nt * 8 + ecol;
            float2 v0 = {acc[mt][nt][0], acc[mt][nt][1]};
            float2 v1 = {acc[mt][nt][2], acc[mt][nt][3]};
            *(float2*)(C + (size_t)r0 * ldc + c0)       = v0;
            *(float2*)(C + (size_t)(r0 + 8) * ldc + c0) = v1;
        }
    }
}

// ---------------- RMSNorm: grid.y=0 -> q slice, grid.y=1 -> k slice ----------------
__global__ __launch_bounds__(256)
void rmsnorm_kernel(float* __restrict__ base, const float* __restrict__ qw,
                    const float* __restrict__ kw)
{
    const int row = blockIdx.x;
    const int tid = threadIdx.x;
    const float* w = (blockIdx.y == 0) ? qw : kw;
    float* xr = base + (size_t)row * NQKV + blockIdx.y * DIM;

    float4 v = *(const float4*)(xr + tid * 4);
    float ss = v.x*v.x + v.y*v.y + v.z*v.z + v.w*v.w;

    __shared__ float red[8];
#pragma unroll
    for (int o = 16; o; o >>= 1) ss += __shfl_xor_sync(0xFFFFFFFFu, ss, o);
    if ((tid & 31) == 0) red[tid >> 5] = ss;
    __syncthreads();
    if (tid < 32) {
        float s = (tid < 8) ? red[tid] : 0.0f;
#pragma unroll
        for (int o = 4; o; o >>= 1) s += __shfl_xor_sync(0xFFFFFFFFu, s, o);
        if (tid == 0) red[0] = s;
    }
    __syncthreads();

    const float rs = rsqrtf(red[0] * (1.0f / DIM) + EPSV);
    float4 wv = *(const float4*)(w + tid * 4);
    v.x *= rs * wv.x; v.y *= rs * wv.y; v.z *= rs * wv.z; v.w *= rs * wv.w;
    *(float4*)(xr + tid * 4) = v;
}

// ---------------- banded attention, smem-staged K/V window; fp16 out ----------------
#define ASMEM (2 * 80 * 132 * 4)

__global__ __launch_bounds__(256)
void attn_kernel(const float* __restrict__ qkv, __half* __restrict__ yh)
{
    extern __shared__ float sm[];
    float* ks = sm;
    float* vs = sm + 80 * 132;
    const int tid  = threadIdx.x;
    const int lane = tid & 31;
    const int wid  = tid >> 5;
    const int qb = blockIdx.x * 64;
    const int h  = blockIdx.y;
    const int b  = blockIdx.z;

    const float* kbase = qkv + (size_t)(b * SEQ) * NQKV + DIM     + h * HD;
    const float* vbase = qkv + (size_t)(b * SEQ) * NQKV + 2 * DIM + h * HD;

    for (int idx = tid; idx < 80 * 32; idx += 256) {
        const int r = idx >> 5, c = idx & 31;
        const int gr = qb - WIN + r;
        if (gr >= 0) {
            ((float4*)(ks + r * 132))[c] = ((const float4*)(kbase + (size_t)gr * NQKV))[c];
            ((float4*)(vs + r * 132))[c] = ((const float4*)(vbase + (size_t)gr * NQKV))[c];
        }
    }
    __syncthreads();

    const float scale = 0.08838834764831845f;   // 1/sqrt(128)
    const float slope = exp2f(-(float)h);       // ALiBi slope, H=8

#pragma unroll 1
    for (int it = 0; it < 8; it++) {
        const int t = qb + it * 8 + wid;
        const float4 q = *(const float4*)(qkv + (size_t)(b * SEQ + t) * NQKV + h * HD + lane * 4);

        float sc[WIN + 1];
        float mx = -1e30f;
#pragma unroll
        for (int jj = 0; jj <= WIN; jj++) {
            const int j = t - WIN + jj;
            float s = -1e30f;
            if (j >= 0) {
                const int sr = j - qb + WIN;
                const float4 k4 = *(const float4*)(ks + sr * 132 + lane * 4);
                float d = q.x*k4.x + q.y*k4.y + q.z*k4.z + q.w*k4.w;
#pragma unroll
                for (int o = 16; o; o >>= 1) d += __shfl_xor_sync(0xFFFFFFFFu, d, o);
                s = d * scale + slope * (float)(j - t);
            }
            sc[jj] = s;
            mx = fmaxf(mx, s);
        }
        float l = 0.0f;
#pragma unroll
        for (int jj = 0; jj <= WIN; jj++) {
            float e = __expf(sc[jj] - mx);
            sc[jj] = e;
            l += e;
        }
        const float inv = 1.0f / l;

        float4 acc = {0.f, 0.f, 0.f, 0.f};
#pragma unroll
        for (int jj = 0; jj <= WIN; jj++) {
            const int j = t - WIN + jj;
            if (j >= 0) {
                const int sr = j - qb + WIN;
                const float4 v4 = *(const float4*)(vs + sr * 132 + lane * 4);
                const float p = sc[jj] * inv;
                acc.x = fmaf(p, v4.x, acc.x);
                acc.y = fmaf(p, v4.y, acc.y);
                acc.z = fmaf(p, v4.z, acc.z);
                acc.w = fmaf(p, v4.w, acc.w);
            }
        }

        const size_t off = (size_t)(b * SEQ + t) * DIM + h * HD + lane * 4;
        __half2 H0; H0.x = __float2half_rn(acc.x); H0.y = __float2half_rn(acc.y);
        __half2 H1; H1.x = __float2half_rn(acc.z); H1.y = __float2half_rn(acc.w);
        ((__half2*)(yh + off))[0] = H0;
        ((__half2*)(yh + off))[1] = H1;
    }
}

// ---------------- launch ----------------
extern "C" void kernel_launch(void* const* d_in, const int* in_sizes, int n_in,
                              void* d_out, int out_size)
{
    const float* x   = (const float*)d_in[0];
    const float* wq  = (const float*)d_in[1];
    const float* wk  = (const float*)d_in[2];
    const float* wv  = (const float*)d_in[3];
    const float* wo  = (const float*)d_in[4];
    const float* qnw = (const float*)d_in[5];
    const float* knw = (const float*)d_in[6];
    float* out       = (float*)d_out;

    __half *wT, *xh, *yh;
    float *qkv;
    cudaGetSymbolAddress((void**)&wT,  g_wT);
    cudaGetSymbolAddress((void**)&xh,  g_xh);
    cudaGetSymbolAddress((void**)&qkv, g_qkv);
    cudaGetSymbolAddress((void**)&yh,  g_yh);

    cudaFuncSetAttribute(gemm_f16,    cudaFuncAttributeMaxDynamicSharedMemorySize, GSMEM);
    cudaFuncSetAttribute(attn_kernel, cudaFuncAttributeMaxDynamicSharedMemorySize, ASMEM);

    // 1) transpose all weights -> fp16 [n][k], rows: [wq|wk|wv|wo]
    dim3 tgrid(DIM/32, DIM/32, 4), tblk(32, 8);
    transpose_all<<<tgrid, tblk>>>(wq, wk, wv, wo, wT);

    // 2) convert x to fp16
    cvt16<<<(MR*DIM/4 + 255)/256, 256>>>(x, xh, MR*DIM/4);

    // 3) fused QKV projection: [8192x1024] @ [1024x3072]
    dim3 qkvgrid(NQKV/128, MR/128);
    gemm_f16<<<qkvgrid, 128, GSMEM>>>(xh, wT, qkv, NQKV);

    // 4) RMSNorm on q and k slices (one launch)
    dim3 ngrid(MR, 2);
    rmsnorm_kernel<<<ngrid, 256>>>(qkv, qnw, knw);

    // 5) banded attention -> y fp16
    dim3 agrid(SEQ/64, NH, BATCH);
    attn_kernel<<<agrid, 256, ASMEM>>>(qkv, yh);

    // 6) output projection: [8192x1024] @ [1024x1024]
    dim3 ogrid(DIM/128, MR/128);
    gemm_f16<<<ogrid, 128, GSMEM>>>(yh, wT + (size_t)3072*DIM, out, DIM);
}

// round 9
// speedup vs baseline: 1.2189x; 1.2189x over previous
#include <cuda_runtime.h>
#include <cuda_fp16.h>
#include <math.h>
#include <stdint.h>

// ---------------- problem constants ----------------
#define BATCH 4
#define SEQ   2048
#define DIM   1024
#define NH    8
#define HD    128
#define WIN   16
#define EPSV  1e-6f
#define MR    (BATCH*SEQ)   // 8192
#define NQKV  3072
#define NW    4096          // transposed weight rows: 3072 qkv + 1024 wo

// ---------------- device scratch ----------------
__device__ __align__(16) __half g_wT[NW*DIM];     // fp16 transposed weights [n][k]
__device__ __align__(16) __half g_xh[MR*DIM];
__device__ __align__(16) float  g_qkv[MR*NQKV];
__device__ __align__(16) __half g_yh[MR*DIM];

// ---------------- PTX helpers ----------------
__device__ __forceinline__ uint32_t smem_u32(const void* p) {
    uint32_t a;
    asm("{ .reg .u64 t; cvta.to.shared.u64 t, %1; cvt.u32.u64 %0, t; }" : "=r"(a) : "l"(p));
    return a;
}
__device__ __forceinline__ void cp16(uint32_t d, const void* s) {
    asm volatile("cp.async.cg.shared.global [%0], [%1], 16;" :: "r"(d), "l"(s));
}
__device__ __forceinline__ void cp_commit() { asm volatile("cp.async.commit_group;" ::: "memory"); }
__device__ __forceinline__ void cp_wait2()  { asm volatile("cp.async.wait_group 2;" ::: "memory"); }
__device__ __forceinline__ void cp_wait1()  { asm volatile("cp.async.wait_group 1;" ::: "memory"); }
__device__ __forceinline__ void cp_wait0()  { asm volatile("cp.async.wait_group 0;" ::: "memory"); }

__device__ __forceinline__ void ldm_x4(uint32_t* r, uint32_t addr) {
    asm volatile("ldmatrix.sync.aligned.m8n8.x4.shared.b16 {%0,%1,%2,%3}, [%4];"
                 : "=r"(r[0]), "=r"(r[1]), "=r"(r[2]), "=r"(r[3]) : "r"(addr));
}
__device__ __forceinline__ void mma_f16(float* c, const uint32_t* a, const uint32_t* b) {
    asm volatile(
        "mma.sync.aligned.m16n8k16.row.col.f32.f16.f16.f32 "
        "{%0,%1,%2,%3}, {%4,%5,%6,%7}, {%8,%9}, {%0,%1,%2,%3};"
        : "+f"(c[0]), "+f"(c[1]), "+f"(c[2]), "+f"(c[3])
        : "r"(a[0]), "r"(a[1]), "r"(a[2]), "r"(a[3]), "r"(b[0]), "r"(b[1]));
}

// ---------------- transpose all 4 weights -> g_wT fp16 [n][k] ----------------
__global__ __launch_bounds__(256)
void transpose_all(const float* __restrict__ wq, const float* __restrict__ wk,
                   const float* __restrict__ wv, const float* __restrict__ wo,
                   __half* __restrict__ wT)
{
    __shared__ float t[32][33];
    const float* W = (blockIdx.z == 0) ? wq : (blockIdx.z == 1) ? wk
                    : (blockIdx.z == 2) ? wv : wo;
    __half* out = wT + (size_t)blockIdx.z * DIM * DIM;
    const int c0 = blockIdx.x * 32, r0 = blockIdx.y * 32;
    const int tx = threadIdx.x, ty = threadIdx.y;
#pragma unroll
    for (int j = 0; j < 4; j++)
        t[ty + 8*j][tx] = W[(size_t)(r0 + ty + 8*j) * DIM + c0 + tx];
    __syncthreads();
#pragma unroll
    for (int j = 0; j < 4; j++)
        out[(size_t)(c0 + ty + 8*j) * DIM + (r0 + tx)] = __float2half_rn(t[tx][ty + 8*j]);
}

// ---------------- fp32 -> fp16 convert ----------------
__global__ __launch_bounds__(256)
void cvt16(const float* __restrict__ x, __half* __restrict__ hi, int n4)
{
    int i = blockIdx.x * 256 + threadIdx.x;
    if (i >= n4) return;
    float4 v = ((const float4*)x)[i];
    __half2 H0; H0.x = __float2half_rn(v.x); H0.y = __float2half_rn(v.y);
    __half2 H1; H1.x = __float2half_rn(v.z); H1.y = __float2half_rn(v.w);
    ((__half2*)hi)[2*i]   = H0;
    ((__half2*)hi)[2*i+1] = H1;
}

// ---------------- fp16 warp-MMA GEMM: C = A @ B^T ----------------
// CTA 128x128, BK=32 fp16, 4-stage cp.async, 8 warps of 32x64, 2 CTAs/SM.
#define TILEB  8192              // 128 rows x 64 bytes
#define STAGEB (2*TILEB)         // A, B
#define GSMEM  (4*STAGEB)        // 65536

__device__ __forceinline__ uint32_t swz_addr(uint32_t tile, int row, int chunk) {
    return tile + row * 64 + (((uint32_t)(chunk ^ ((row >> 1) & 3))) << 4);
}
__device__ __forceinline__ void ld_tile(uint32_t sdst, const __half* g,
                                        int grow0, int k0, int lrow, int lc0)
{
    const __half* src = g + (size_t)(grow0 + lrow) * DIM + k0 + lc0 * 8;
    cp16(swz_addr(sdst, lrow, lc0),     src);
    cp16(swz_addr(sdst, lrow, lc0 + 1), src + 8);
}

__global__ __launch_bounds__(256, 2)
void gemm_f16(const __half* __restrict__ a, const __half* __restrict__ b,
              float* __restrict__ C, int ldc)
{
    extern __shared__ char smem[];
    const uint32_t sbase = smem_u32(smem);
    const int tid  = threadIdx.x;
    const int lane = tid & 31;
    const int wid  = tid >> 5;
    const int wm   = wid >> 1;          // 0..3 -> 32-row strip
    const int wn   = wid & 1;           // 0..1 -> 64-col strip
    const int m0 = blockIdx.y * 128;
    const int n0 = blockIdx.x * 128;

    const int lrow = tid >> 1;          // 0..127
    const int lc0  = (tid & 1) * 2;     // 0 or 2

    // fragment addressing
    int arow[2], browx[4];
#pragma unroll
    for (int mt = 0; mt < 2; mt++) arow[mt] = wm * 32 + mt * 16 + (lane & 15);
#pragma unroll
    for (int p = 0; p < 4; p++)
        browx[p] = wn * 64 + p * 16 + ((lane >> 4) << 3) + (lane & 7);
    const int ac = lane >> 4;           // A chunk selector
    const int bc = (lane >> 3) & 1;     // B chunk selector

    float acc[2][8][4];
#pragma unroll
    for (int mt = 0; mt < 2; mt++)
#pragma unroll
        for (int nt = 0; nt < 8; nt++)
#pragma unroll
            for (int q = 0; q < 4; q++) acc[mt][nt][q] = 0.0f;

#pragma unroll
    for (int s = 0; s < 3; s++) {
        const uint32_t st = sbase + s * STAGEB;
        const int k0 = s * 32;
        ld_tile(st,         a, m0, k0, lrow, lc0);
        ld_tile(st + TILEB, b, n0, k0, lrow, lc0);
        cp_commit();
    }

    const int NIT = DIM / 32;           // 32
    for (int i = 0; i < NIT; i++) {
        if (i < NIT - 2)      cp_wait2();
        else if (i == NIT-2)  cp_wait1();
        else                  cp_wait0();
        __syncthreads();

        if (i + 3 < NIT) {
            const uint32_t st = sbase + ((i + 3) & 3) * STAGEB;
            const int k0 = (i + 3) * 32;
            ld_tile(st,         a, m0, k0, lrow, lc0);
            ld_tile(st + TILEB, b, n0, k0, lrow, lc0);
            cp_commit();
        }

        const uint32_t st = sbase + (i & 3) * STAGEB;
        const uint32_t sA = st;
        const uint32_t sB = st + TILEB;

#pragma unroll
        for (int kh = 0; kh < 2; kh++) {
            uint32_t fB[4][4], fA[2][4];
#pragma unroll
            for (int p = 0; p < 4; p++)
                ldm_x4(fB[p], swz_addr(sB, browx[p], kh * 2 + bc));
#pragma unroll
            for (int mt = 0; mt < 2; mt++)
                ldm_x4(fA[mt], swz_addr(sA, arow[mt], kh * 2 + ac));
#pragma unroll
            for (int mt = 0; mt < 2; mt++)
#pragma unroll
                for (int p = 0; p < 4; p++) {
                    mma_f16(acc[mt][p*2],     fA[mt], &fB[p][0]);
                    mma_f16(acc[mt][p*2 + 1], fA[mt], &fB[p][2]);
                }
        }
    }

    const int erow = lane >> 2;
    const int ecol = (lane & 3) * 2;
#pragma unroll
    for (int mt = 0; mt < 2; mt++) {
#pragma unroll
        for (int nt = 0; nt < 8; nt++) {
            const int r0 = m0 + wm * 32 + mt * 16 + erow;
            const int c0 = n0 + wn * 64 + nt * 8 + ecol;
            float2 v0 = {acc[mt][nt][0], acc[mt][nt][1]};
            float2 v1 = {acc[mt][nt][2], acc[mt][nt][3]};
            *(float2*)(C + (size_t)r0 * ldc + c0)       = v0;
            *(float2*)(C + (size_t)(r0 + 8) * ldc + c0) = v1;
        }
    }
}

// ---------------- RMSNorm: grid.y=0 -> q slice, grid.y=1 -> k slice ----------------
__global__ __launch_bounds__(256)
void rmsnorm_kernel(float* __restrict__ base, const float* __restrict__ qw,
                    const float* __restrict__ kw)
{
    const int row = blockIdx.x;
    const int tid = threadIdx.x;
    const float* w = (blockIdx.y == 0) ? qw : kw;
    float* xr = base + (size_t)row * NQKV + blockIdx.y * DIM;

    float4 v = *(const float4*)(xr + tid * 4);
    float ss = v.x*v.x + v.y*v.y + v.z*v.z + v.w*v.w;

    __shared__ float red[8];
#pragma unroll
    for (int o = 16; o; o >>= 1) ss += __shfl_xor_sync(0xFFFFFFFFu, ss, o);
    if ((tid & 31) == 0) red[tid >> 5] = ss;
    __syncthreads();
    if (tid < 32) {
        float s = (tid < 8) ? red[tid] : 0.0f;
#pragma unroll
        for (int o = 4; o; o >>= 1) s += __shfl_xor_sync(0xFFFFFFFFu, s, o);
        if (tid == 0) red[0] = s;
    }
    __syncthreads();

    const float rs = rsqrtf(red[0] * (1.0f / DIM) + EPSV);
    float4 wv = *(const float4*)(w + tid * 4);
    v.x *= rs * wv.x; v.y *= rs * wv.y; v.z *= rs * wv.z; v.w *= rs * wv.w;
    *(float4*)(xr + tid * 4) = v;
}

// ---------------- banded attention, smem-staged K/V window; fp16 out ----------------
#define ASMEM (2 * 80 * 132 * 4)

__global__ __launch_bounds__(256)
void attn_kernel(const float* __restrict__ qkv, __half* __restrict__ yh)
{
    extern __shared__ float sm[];
    float* ks = sm;
    float* vs = sm + 80 * 132;
    const int tid  = threadIdx.x;
    const int lane = tid & 31;
    const int wid  = tid >> 5;
    const int qb = blockIdx.x * 64;
    const int h  = blockIdx.y;
    const int b  = blockIdx.z;

    const float* kbase = qkv + (size_t)(b * SEQ) * NQKV + DIM     + h * HD;
    const float* vbase = qkv + (size_t)(b * SEQ) * NQKV + 2 * DIM + h * HD;

    for (int idx = tid; idx < 80 * 32; idx += 256) {
        const int r = idx >> 5, c = idx & 31;
        const int gr = qb - WIN + r;
        if (gr >= 0) {
            ((float4*)(ks + r * 132))[c] = ((const float4*)(kbase + (size_t)gr * NQKV))[c];
            ((float4*)(vs + r * 132))[c] = ((const float4*)(vbase + (size_t)gr * NQKV))[c];
        }
    }
    __syncthreads();

    const float scale = 0.08838834764831845f;   // 1/sqrt(128)
    const float slope = exp2f(-(float)h);       // ALiBi slope, H=8

#pragma unroll 1
    for (int it = 0; it < 8; it++) {
        const int t = qb + it * 8 + wid;
        const float4 q = *(const float4*)(qkv + (size_t)(b * SEQ + t) * NQKV + h * HD + lane * 4);

        float sc[WIN + 1];
        float mx = -1e30f;
#pragma unroll
        for (int jj = 0; jj <= WIN; jj++) {
            const int j = t - WIN + jj;
            float s = -1e30f;
            if (j >= 0) {
                const int sr = j - qb + WIN;
                const float4 k4 = *(const float4*)(ks + sr * 132 + lane * 4);
                float d = q.x*k4.x + q.y*k4.y + q.z*k4.z + q.w*k4.w;
#pragma unroll
                for (int o = 16; o; o >>= 1) d += __shfl_xor_sync(0xFFFFFFFFu, d, o);
                s = d * scale + slope * (float)(j - t);
            }
            sc[jj] = s;
            mx = fmaxf(mx, s);
        }
        float l = 0.0f;
#pragma unroll
        for (int jj = 0; jj <= WIN; jj++) {
            float e = __expf(sc[jj] - mx);
            sc[jj] = e;
            l += e;
        }
        const float inv = 1.0f / l;

        float4 acc = {0.f, 0.f, 0.f, 0.f};
#pragma unroll
        for (int jj = 0; jj <= WIN; jj++) {
            const int j = t - WIN + jj;
            if (j >= 0) {
                const int sr = j - qb + WIN;
                const float4 v4 = *(const float4*)(vs + sr * 132 + lane * 4);
                const float p = sc[jj] * inv;
                acc.x = fmaf(p, v4.x, acc.x);
                acc.y = fmaf(p, v4.y, acc.y);
                acc.z = fmaf(p, v4.z, acc.z);
                acc.w = fmaf(p, v4.w, acc.w);
            }
        }

        const size_t off = (size_t)(b * SEQ + t) * DIM + h * HD + lane * 4;
        __half2 H0; H0.x = __float2half_rn(acc.x); H0.y = __float2half_rn(acc.y);
        __half2 H1; H1.x = __float2half_rn(acc.z); H1.y = __float2half_rn(acc.w);
        ((__half2*)(yh + off))[0] = H0;
        ((__half2*)(yh + off))[1] = H1;
    }
}

// ---------------- launch ----------------
extern "C" void kernel_launch(void* const* d_in, const int* in_sizes, int n_in,
                              void* d_out, int out_size)
{
    const float* x   = (const float*)d_in[0];
    const float* wq  = (const float*)d_in[1];
    const float* wk  = (const float*)d_in[2];
    const float* wv  = (const float*)d_in[3];
    const float* wo  = (const float*)d_in[4];
    const float* qnw = (const float*)d_in[5];
    const float* knw = (const float*)d_in[6];
    float* out       = (float*)d_out;

    __half *wT, *xh, *yh;
    float *qkv;
    cudaGetSymbolAddress((void**)&wT,  g_wT);
    cudaGetSymbolAddress((void**)&xh,  g_xh);
    cudaGetSymbolAddress((void**)&qkv, g_qkv);
    cudaGetSymbolAddress((void**)&yh,  g_yh);

    cudaFuncSetAttribute(gemm_f16,    cudaFuncAttributeMaxDynamicSharedMemorySize, GSMEM);
    cudaFuncSetAttribute(attn_kernel, cudaFuncAttributeMaxDynamicSharedMemorySize, ASMEM);

    // 1) transpose all weights -> fp16 [n][k], rows: [wq|wk|wv|wo]
    dim3 tgrid(DIM/32, DIM/32, 4), tblk(32, 8);
    transpose_all<<<tgrid, tblk>>>(wq, wk, wv, wo, wT);

    // 2) convert x to fp16
    cvt16<<<(MR*DIM/4 + 255)/256, 256>>>(x, xh, MR*DIM/4);

    // 3) fused QKV projection: [8192x1024] @ [1024x3072]
    dim3 qkvgrid(NQKV/128, MR/128);
    gemm_f16<<<qkvgrid, 256, GSMEM>>>(xh, wT, qkv, NQKV);

    // 4) RMSNorm on q and k slices (one launch)
    dim3 ngrid(MR, 2);
    rmsnorm_kernel<<<ngrid, 256>>>(qkv, qnw, knw);

    // 5) banded attention -> y fp16
    dim3 agrid(SEQ/64, NH, BATCH);
    attn_kernel<<<agrid, 256, ASMEM>>>(qkv, yh);

    // 6) output projection: [8192x1024] @ [1024x1024]
    dim3 ogrid(DIM/128, MR/128);
    gemm_f16<<<ogrid, 256, GSMEM>>>(yh, wT + (size_t)3072*DIM, out, DIM);
}